// round 15
// baseline (speedup 1.0000x reference)
#include <cuda_runtime.h>
#include <cuda_fp16.h>
#include <math.h>
#include <stdint.h>

#define Bb 8
#define Nn 2048
#define Ff 64
#define MTILE 64
#define JT 64
#define NSTEPS (Nn / JT)        // 32
#define JSPLIT 2
#define SPLIT_STEPS (NSTEPS / JSPLIT)   // 16

#define PREP_CTAS 512           // 32 rows each
#define PACK_CTAS 512           // 4 adj rows each

typedef unsigned long long ull;

// Scratch (device globals)
__device__ __half g_WhT[Bb * Ff * Nn];    // 2 MB f16  [b][f][j]
__device__ float4 g_e1pack[Bb * Nn];
__device__ float4 g_e2pack[Bb * Nn];
__device__ ull    g_adjmask[Nn * (Nn / 64)];
__device__ float  g_accS[JSPLIT * Bb * Nn * Ff];  // 8 MB partial numerators
__device__ float  g_Zp[JSPLIT * Bb * Nn];         // partial denominators

// ------------------------- helpers ----------------------------
__device__ __forceinline__ uint32_t smem_u32(const void* p) {
    uint32_t a;
    asm("{ .reg .u64 t; cvta.to.shared.u64 t, %1; cvt.u32.u64 %0, t; }" : "=r"(a) : "l"(p));
    return a;
}
__device__ __forceinline__ uint32_t swz128(uint32_t off) {
    return off ^ ((off >> 3) & 0x70);
}
__device__ __forceinline__ void cp16(uint32_t dst, const void* src) {
    asm volatile("cp.async.cg.shared.global [%0], [%1], 16;" :: "r"(dst), "l"(src));
}
#define CP_COMMIT() asm volatile("cp.async.commit_group;" ::: "memory")
#define CP_WAIT0()  asm volatile("cp.async.wait_group 0;" ::: "memory")
__device__ __forceinline__ void ldsm_x4(uint32_t& r0, uint32_t& r1, uint32_t& r2, uint32_t& r3,
                                        uint32_t addr) {
    asm volatile("ldmatrix.sync.aligned.m8n8.x4.shared.b16 {%0,%1,%2,%3}, [%4];"
                 : "=r"(r0), "=r"(r1), "=r"(r2), "=r"(r3) : "r"(addr));
}
__device__ __forceinline__ void mma16816(float* c, const uint32_t* a, const uint32_t* bf) {
    asm volatile(
        "mma.sync.aligned.m16n8k16.row.col.f32.f16.f16.f32 "
        "{%0,%1,%2,%3}, {%4,%5,%6,%7}, {%8,%9}, {%0,%1,%2,%3};"
        : "+f"(c[0]), "+f"(c[1]), "+f"(c[2]), "+f"(c[3])
        : "r"(a[0]), "r"(a[1]), "r"(a[2]), "r"(a[3]), "r"(bf[0]), "r"(bf[1]));
}

// ---------------------------------------------------------------------------
// Kernel 1 (merged prep + bitpack) — unchanged from R14.
// ---------------------------------------------------------------------------
__global__ __launch_bounds__(128) void prep_pack_kernel(const float* __restrict__ h,
                                                        const float* __restrict__ W,
                                                        const float* __restrict__ a,
                                                        const float* __restrict__ adj)
{
    const int t    = threadIdx.x;
    const int lane = t & 31;
    const int w    = t >> 5;

    if (blockIdx.x >= PREP_CTAS) {
        const int row = (blockIdx.x - PREP_CTAS) * 4 + w;
        uint32_t* mw = (uint32_t*)g_adjmask;
        const float* arow = adj + (size_t)row * Nn;
#pragma unroll 4
        for (int c = 0; c < 64; c++) {
            float av = __ldg(&arow[c * 32 + lane]);
            uint32_t m = __ballot_sync(0xffffffffu, av > 0.f);
            if (lane == 0) mw[row * 64 + c] = m;
        }
        return;
    }

    __shared__ __align__(128) char reg1[16384];
    __shared__ __align__(128) char reg2[8192];
    __shared__ __align__(128) __half B_s[64 * 64];
    __shared__ float u1_s[64], u2_s[64];

    float* W32 = (float*)reg1;
    float* h32 = (float*)reg2;
    __half* tT = (__half*)reg2;

    const int row0 = blockIdx.x * 32;

    const uint32_t r1b = smem_u32(reg1);
    const uint32_t r2b = smem_u32(reg2);
    const uint32_t Bsb = smem_u32(B_s);

    {
        const char* Wsrc = (const char*)W;
        const char* hsrc = (const char*)(h + (size_t)row0 * 64);
#pragma unroll
        for (int q = 0; q < 8; q++)
            cp16(r1b + (t + q * 128) * 16, Wsrc + (t + q * 128) * 16);
#pragma unroll
        for (int q = 0; q < 4; q++)
            cp16(r2b + (t + q * 128) * 16, hsrc + (t + q * 128) * 16);
        CP_COMMIT();
        CP_WAIT0();
    }
    __syncthreads();

    {
        const int o = t >> 1, fh = (t & 1) * 32;
        const float* src = W32 + o * 64 + fh;
#pragma unroll
        for (int fo = 0; fo < 16; fo++) {
            float2 v = *(const float2*)(src + 2 * fo);
            *(__half2*)((char*)B_s + swz128((uint32_t)(o * 128 + fh * 2 + fo * 4))) =
                __floats2half2_rn(v.x, v.y);
        }
        const int half = t >> 6, f = t & 63;
        const float* ap = a + half * 64;
        float acc = 0.f;
#pragma unroll 8
        for (int o2 = 0; o2 < 64; o2++)
            acc += W32[o2 * 64 + f] * __ldg(&ap[o2]);
        if (half == 0) u1_s[f] = acc; else u2_s[f] = acc;
    }
    __syncthreads();

    {
        const int r = t >> 2, fh = (t & 3) * 16;
        const float* src = h32 + r * 64 + fh;
        float acc1 = 0.f, acc2 = 0.f;
#pragma unroll
        for (int fo = 0; fo < 8; fo++) {
            float2 v = *(const float2*)(src + 2 * fo);
            int f = fh + 2 * fo;
            acc1 += v.x * u1_s[f] + v.y * u1_s[f + 1];
            acc2 += v.x * u2_s[f] + v.y * u2_s[f + 1];
            *(__half2*)((char*)reg1 + swz128((uint32_t)(r * 128 + fh * 2 + fo * 4))) =
                __floats2half2_rn(v.x, v.y);
        }
        acc1 += __shfl_xor_sync(0xffffffffu, acc1, 1);
        acc1 += __shfl_xor_sync(0xffffffffu, acc1, 2);
        acc2 += __shfl_xor_sync(0xffffffffu, acc2, 1);
        acc2 += __shfl_xor_sync(0xffffffffu, acc2, 2);
        if ((t & 3) == 0) {
            g_e1pack[row0 + r] = make_float4(acc1, __expf(acc1), __expf(0.2f * acc1), 0.f);
            g_e2pack[row0 + r] = make_float4(acc2, __expf(acc2), __expf(0.2f * acc2), 0.f);
        }
    }
    __syncthreads();

    float acc[4][4];
#pragma unroll
    for (int nf = 0; nf < 4; nf++)
#pragma unroll
        for (int c = 0; c < 4; c++) acc[nf][c] = 0.f;

    const int wm = w & 1, wn = w >> 1;
    {
        const uint32_t xv = (lane & 7) << 4;
        const uint32_t aRowOff = (uint32_t)(wm * 16 + (lane & 7) + ((lane >> 3) & 1) * 8) * 128;
        const uint32_t akbo    = ((lane >> 4) & 1) * 16;
        const uint32_t bRow4   = (uint32_t)(wn * 32 + ((lane >> 4) & 1) * 8 + (lane & 7)) * 128;
        const uint32_t bkb4    = ((lane >> 3) & 1) * 16;
#pragma unroll
        for (int kf = 0; kf < 4; kf++) {
            const uint32_t kb = kf * 32;
            uint32_t a4[4];
            ldsm_x4(a4[0], a4[1], a4[2], a4[3], r1b + aRowOff + ((kb + akbo) ^ xv));
#pragma unroll
            for (int p = 0; p < 2; p++) {
                uint32_t bfr[4];
                ldsm_x4(bfr[0], bfr[1], bfr[2], bfr[3],
                        Bsb + bRow4 + p * 2048 + ((kb + bkb4) ^ xv));
                mma16816(acc[2 * p],     a4, bfr);
                mma16816(acc[2 * p + 1], a4, bfr + 2);
            }
        }
    }
    __syncthreads();

    {
        const int r_lo = wm * 16 + (lane >> 2);
        const int r_hi = r_lo + 8;
#pragma unroll
        for (int nf = 0; nf < 4; nf++) {
            const int c0 = wn * 32 + nf * 8 + 2 * (lane & 3);
            tT[(c0 + 0) * 40 + r_lo] = __float2half_rn(acc[nf][0]);
            tT[(c0 + 1) * 40 + r_lo] = __float2half_rn(acc[nf][1]);
            tT[(c0 + 0) * 40 + r_hi] = __float2half_rn(acc[nf][2]);
            tT[(c0 + 1) * 40 + r_hi] = __float2half_rn(acc[nf][3]);
        }
    }
    __syncthreads();

    {
        const int b  = row0 / Nn;
        const int i0 = row0 % Nn;
        const int o  = t >> 1;
        const int rp = (t & 1) * 16;
        __half* dst = g_WhT + ((size_t)b * Ff + o) * Nn + i0 + rp;
        *(uint4*)(dst)     = *(const uint4*)&tT[o * 40 + rp];
        *(uint4*)(dst + 8) = *(const uint4*)&tT[o * 40 + rp + 8];
    }
}

// ---------------------------------------------------------------------------
// Kernel 2: split-j GAT main. grid (32, 8, JSPLIT) = 512 CTAs; each runs 16
// j-steps and writes partial numerator + partial Z to scratch.
// ---------------------------------------------------------------------------
__global__ __launch_bounds__(256, 2) void gat_hmma(void)
{
    __shared__ __align__(128) __half A_s[2][MTILE * 64];
    __shared__ __align__(128) __half B_s[2][64 * 64];
    __shared__ float e1_s[MTILE], E1p_s[MTILE], E1n_s[MTILE];

    const int t    = threadIdx.x;
    const int lane = t & 31;
    const int wid  = t >> 5;      // 0..7
    const int wm   = wid & 3;
    const int wn   = wid >> 2;
    const int i0   = blockIdx.x * MTILE;
    const int b    = blockIdx.y;
    const int js   = blockIdx.z;
    const int s0   = js * SPLIT_STEPS;

    if (t < MTILE) {
        float4 p = g_e1pack[(size_t)b * Nn + i0 + t];
        e1_s[t] = p.x; E1p_s[t] = p.y; E1n_s[t] = p.z;
    }
    __syncthreads();

    const uint32_t Abase = smem_u32(A_s);
    const uint32_t Bbase = smem_u32(B_s);

    const uint32_t xv = (lane & 7) << 4;
    const uint32_t aRowOff = (uint32_t)(wm * 16 + (lane & 7) + ((lane >> 3) & 1) * 8) * 128;
    const uint32_t akbo    = ((lane >> 4) & 1) * 16;
    const uint32_t bRow4   = (uint32_t)(wn * 32 + ((lane >> 4) & 1) * 8 + (lane & 7)) * 128;
    const uint32_t bkb4    = ((lane >> 3) & 1) * 16;

    const __half* whtB = g_WhT + (size_t)b * Ff * Nn;
    const float4* e2p  = g_e2pack + (size_t)b * Nn;

    const int bf1 = t >> 3, bc1 = t & 7;
    const int bf2 = (t + 256) >> 3;
    const uint32_t bDst1 = Bbase + swz128((uint32_t)(bf1 * 128 + bc1 * 16));
    const uint32_t bDst2 = Bbase + swz128((uint32_t)(bf2 * 128 + bc1 * 16));
    const __half* bSrc1 = whtB + (size_t)bf1 * Nn + bc1 * 8;
    const __half* bSrc2 = whtB + (size_t)bf2 * Nn + bc1 * 8;

#define CPB(S, BUF) do {                                  \
        cp16(bDst1 + (BUF) * 8192, bSrc1 + (S) * JT);     \
        cp16(bDst2 + (BUF) * 8192, bSrc2 + (S) * JT);     \
        CP_COMMIT();                                      \
    } while (0)

    float acc[4][4];
#pragma unroll
    for (int nf = 0; nf < 4; nf++)
#pragma unroll
        for (int c = 0; c < 4; c++) acc[nf][c] = 0.f;

    float zpart[8];
#pragma unroll
    for (int g = 0; g < 8; g++) zpart[g] = 0.f;

#define LOAD_SET(S, JP0, JP1, MM) do {                                           \
        JP0 = __ldg(&e2p[(S) * JT + 2 * lane]);                                  \
        JP1 = __ldg(&e2p[(S) * JT + 2 * lane + 1]);                              \
        _Pragma("unroll")                                                        \
        for (int g = 0; g < 8; g++)                                              \
            MM[g] = __ldg(&g_adjmask[(size_t)(i0 + wid * 8 + g) * (Nn / 64) + (S)]); \
    } while (0)

#define PGEN_C(JP0, JP1, MM, BUF) do {                                           \
        _Pragma("unroll")                                                        \
        for (int g = 0; g < 8; g++) {                                            \
            int i = wid * 8 + g;                                                 \
            float e1v = e1_s[i], e1pv = E1p_s[i], e1nv = E1n_s[i];               \
            float p0 = (e1v + JP0.x > 0.f) ? e1pv * JP0.y : e1nv * JP0.z;        \
            float p1 = (e1v + JP1.x > 0.f) ? e1pv * JP1.y : e1nv * JP1.z;        \
            p0 = ((MM[g] >> (2 * lane)) & 1ull)     ? p0 : 0.f;                  \
            p1 = ((MM[g] >> (2 * lane + 1)) & 1ull) ? p1 : 0.f;                  \
            __half2 ph = __floats2half2_rn(p0, p1);                              \
            float2 pf = __half22float2(ph);                                      \
            zpart[g] += pf.x + pf.y;                                             \
            *(__half2*)((char*)A_s + (BUF) * 8192 +                              \
                        swz128((uint32_t)(i * 128 + lane * 4))) = ph;            \
        }                                                                        \
    } while (0)

#define HMMA(BUF) do {                                                           \
        const uint32_t Ab_ = Abase + (BUF) * 8192;                               \
        const uint32_t Bb_ = Bbase + (BUF) * 8192;                               \
        _Pragma("unroll")                                                        \
        for (int kf = 0; kf < 4; kf++) {                                         \
            const uint32_t kb = kf * 32;                                         \
            uint32_t a4[4];                                                      \
            ldsm_x4(a4[0], a4[1], a4[2], a4[3], Ab_ + aRowOff + ((kb + akbo) ^ xv)); \
            _Pragma("unroll")                                                    \
            for (int p = 0; p < 2; p++) {                                        \
                uint32_t bfr[4];                                                 \
                ldsm_x4(bfr[0], bfr[1], bfr[2], bfr[3],                          \
                        Bb_ + bRow4 + p * 2048 + ((kb + bkb4) ^ xv));            \
                mma16816(acc[2 * p],     a4, bfr);                               \
                mma16816(acc[2 * p + 1], a4, bfr + 2);                           \
            }                                                                    \
        }                                                                        \
    } while (0)

    float4 jpA0, jpA1, jpB0, jpB1;
    ull mA[8], mB[8];

    CPB(s0, 0);
    LOAD_SET(s0, jpA0, jpA1, mA);
    PGEN_C(jpA0, jpA1, mA, 0);
    LOAD_SET(s0 + 1, jpB0, jpB1, mB);

#pragma unroll 1
    for (int s = s0; s < s0 + SPLIT_STEPS; s += 2) {
        CP_WAIT0();
        __syncthreads();
        CPB(s + 1, 1);
        PGEN_C(jpB0, jpB1, mB, 1);
        if (s + 2 < s0 + SPLIT_STEPS) LOAD_SET(s + 2, jpA0, jpA1, mA);
        HMMA(0);

        CP_WAIT0();
        __syncthreads();
        if (s + 2 < s0 + SPLIT_STEPS) {
            CPB(s + 2, 0);
            PGEN_C(jpA0, jpA1, mA, 0);
            if (s + 3 < s0 + SPLIT_STEPS) LOAD_SET(s + 3, jpB0, jpB1, mB);
        }
        HMMA(1);
    }
#undef CPB
#undef LOAD_SET
#undef PGEN_C
#undef HMMA

    // partial Z -> scratch (warp wid owns rows wid*8..+7)
#pragma unroll
    for (int g = 0; g < 8; g++) {
        float z = zpart[g];
#pragma unroll
        for (int off = 16; off; off >>= 1)
            z += __shfl_xor_sync(0xffffffffu, z, off);
        if (lane == 0)
            g_Zp[((size_t)js * Bb + b) * Nn + i0 + wid * 8 + g] = z;
    }

    // partial numerator -> scratch (raw acc, no normalize)
    {
        const int r_lo = wm * 16 + (lane >> 2);
        const int r_hi = r_lo + 8;
        float* base = g_accS + (((size_t)js * Bb + b) * Nn + i0) * 64;
        float* olo = base + (size_t)r_lo * 64;
        float* ohi = base + (size_t)r_hi * 64;
#pragma unroll
        for (int nf = 0; nf < 4; nf++) {
            const int col = wn * 32 + nf * 8 + 2 * (lane & 3);
            *(float2*)(olo + col) = make_float2(acc[nf][0], acc[nf][1]);
            *(float2*)(ohi + col) = make_float2(acc[nf][2], acc[nf][3]);
        }
    }
}

// ---------------------------------------------------------------------------
// Kernel 3: combine 2 splits, normalize, ELU, store.
// 262144 float4 -> 1024 CTAs x 256.
// ---------------------------------------------------------------------------
__global__ __launch_bounds__(256) void combine_kernel(float* __restrict__ out)
{
    const int gid = blockIdx.x * 256 + threadIdx.x;     // float4 index
    const float4* a4 = (const float4*)g_accS;
    const int STRIDE = Bb * Nn * Ff / 4;

    float4 s0 = a4[gid];
    float4 s1 = a4[gid + STRIDE];
    const int row = gid >> 4;
    const float zinv = 1.0f / (g_Zp[row] + g_Zp[row + Bb * Nn]);

    float4 v;
    v.x = (s0.x + s1.x) * zinv;
    v.y = (s0.y + s1.y) * zinv;
    v.z = (s0.z + s1.z) * zinv;
    v.w = (s0.w + s1.w) * zinv;
    v.x = v.x > 0.f ? v.x : expm1f(v.x);
    v.y = v.y > 0.f ? v.y : expm1f(v.y);
    v.z = v.z > 0.f ? v.z : expm1f(v.z);
    v.w = v.w > 0.f ? v.w : expm1f(v.w);
    ((float4*)out)[gid] = v;
}

// ---------------------------------------------------------------------------
extern "C" void kernel_launch(void* const* d_in, const int* in_sizes, int n_in,
                              void* d_out, int out_size)
{
    const float* h = nullptr; const float* adj = nullptr;
    const float* W = nullptr; const float* a = nullptr;
    for (int i = 0; i < n_in; i++) {
        switch (in_sizes[i]) {
            case Bb * Nn * Ff: h   = (const float*)d_in[i]; break;
            case Nn * Nn:      adj = (const float*)d_in[i]; break;
            case Ff * Ff:      W   = (const float*)d_in[i]; break;
            case 2 * Ff:       a   = (const float*)d_in[i]; break;
            default: break;
        }
    }
    (void)out_size;

    prep_pack_kernel<<<PREP_CTAS + PACK_CTAS, 128>>>(h, W, a, adj);
    gat_hmma<<<dim3(Nn / MTILE, Bb, JSPLIT), 256>>>();
    combine_kernel<<<(Bb * Nn * Ff) / 4 / 256, 256>>>((float*)d_out);
}

// round 16
// speedup vs baseline: 1.0846x; 1.0846x over previous
#include <cuda_runtime.h>
#include <cuda_fp16.h>
#include <math.h>
#include <stdint.h>

#define Bb 8
#define Nn 2048
#define Ff 64
#define MTILE 64
#define JT 64
#define NSTEPS (Nn / JT)        // 32

#define PREP_CTAS 256           // 64 rows each
#define PACK_CTAS 256           // 8 adj rows each

typedef unsigned long long ull;

// Scratch (device globals)
__device__ __half g_WhT[Bb * Ff * Nn];    // 2 MB f16  [b][f][j]
__device__ float4 g_e1pack[Bb * Nn];      // (e1, exp(e1), exp(0.2 e1), 0)
__device__ float4 g_e2pack[Bb * Nn];
__device__ ull    g_adjmask[Nn * (Nn / 64)];

// ------------------------- helpers ----------------------------
__device__ __forceinline__ uint32_t smem_u32(const void* p) {
    uint32_t a;
    asm("{ .reg .u64 t; cvta.to.shared.u64 t, %1; cvt.u32.u64 %0, t; }" : "=r"(a) : "l"(p));
    return a;
}
__device__ __forceinline__ uint32_t swz128(uint32_t off) {
    return off ^ ((off >> 3) & 0x70);
}
__device__ __forceinline__ void cp16(uint32_t dst, const void* src) {
    asm volatile("cp.async.cg.shared.global [%0], [%1], 16;" :: "r"(dst), "l"(src));
}
#define CP_COMMIT() asm volatile("cp.async.commit_group;" ::: "memory")
#define CP_WAIT0()  asm volatile("cp.async.wait_group 0;" ::: "memory")
__device__ __forceinline__ void ldsm_x4(uint32_t& r0, uint32_t& r1, uint32_t& r2, uint32_t& r3,
                                        uint32_t addr) {
    asm volatile("ldmatrix.sync.aligned.m8n8.x4.shared.b16 {%0,%1,%2,%3}, [%4];"
                 : "=r"(r0), "=r"(r1), "=r"(r2), "=r"(r3) : "r"(addr));
}
__device__ __forceinline__ void mma16816(float* c, const uint32_t* a, const uint32_t* bf) {
    asm volatile(
        "mma.sync.aligned.m16n8k16.row.col.f32.f16.f16.f32 "
        "{%0,%1,%2,%3}, {%4,%5,%6,%7}, {%8,%9}, {%0,%1,%2,%3};"
        : "+f"(c[0]), "+f"(c[1]), "+f"(c[2]), "+f"(c[3])
        : "r"(a[0]), "r"(a[1]), "r"(a[2]), "r"(a[3]), "r"(bf[0]), "r"(bf[1]));
}

// ---------------------------------------------------------------------------
// Kernel 1 (merged): CTAs [0, PREP_CTAS): Wh/e-pack prep, 64 rows, 256 thr.
//                    CTAs [PREP_CTAS, +PACK_CTAS): adj bitmask, 8 rows each.
// ---------------------------------------------------------------------------
__global__ __launch_bounds__(256) void prep_pack_kernel(const float* __restrict__ h,
                                                        const float* __restrict__ W,
                                                        const float* __restrict__ a,
                                                        const float* __restrict__ adj)
{
    const int t    = threadIdx.x;
    const int lane = t & 31;
    const int w    = t >> 5;      // 0..7

    if (blockIdx.x >= PREP_CTAS) {
        // ---------------- bitpack: 8 rows per CTA ----------------
        const int row = (blockIdx.x - PREP_CTAS) * 8 + w;
        uint32_t* mw = (uint32_t*)g_adjmask;
        const float* arow = adj + (size_t)row * Nn;
#pragma unroll 4
        for (int c = 0; c < 64; c++) {
            float av = __ldg(&arow[c * 32 + lane]);
            uint32_t m = __ballot_sync(0xffffffffu, av > 0.f);
            if (lane == 0) mw[row * 64 + c] = m;
        }
        return;
    }

    // ---------------- prep: 64 rows per CTA, 8 warps ----------------
    __shared__ __align__(128) char reg1[16384];    // W32 (fp32) -> A_s (f16 swz, 8 KB)
    __shared__ __align__(128) char reg2[16384];    // h32 (fp32) -> tT (f16 [o][72])
    __shared__ __align__(128) __half B_s[64 * 64]; // 8 KB swz
    __shared__ float u1_s[64], u2_s[64];

    float* W32 = (float*)reg1;
    float* h32 = (float*)reg2;
    __half* tT = (__half*)reg2;                    // stride 72 halfs (144 B rows)

    const int row0 = blockIdx.x * 64;              // global row in [0, 16384)

    const uint32_t r1b = smem_u32(reg1);
    const uint32_t r2b = smem_u32(reg2);
    const uint32_t Bsb = smem_u32(B_s);

    // stage W (16 KB) + h (16 KB)
    {
        const char* Wsrc = (const char*)W;
        const char* hsrc = (const char*)(h + (size_t)row0 * 64);
#pragma unroll
        for (int q = 0; q < 4; q++) {
            cp16(r1b + (t + q * 256) * 16, Wsrc + (t + q * 256) * 16);
            cp16(r2b + (t + q * 256) * 16, hsrc + (t + q * 256) * 16);
        }
        CP_COMMIT();
        CP_WAIT0();
    }
    __syncthreads();

    // phase 1: B = f16(W32) swizzled; u1/u2 = W^T a (threads 0..127)
    {
        const int o = t >> 2, fh = (t & 3) * 16;
        const float* src = W32 + o * 64 + fh;
#pragma unroll
        for (int fo = 0; fo < 8; fo++) {
            float2 v = *(const float2*)(src + 2 * fo);
            *(__half2*)((char*)B_s + swz128((uint32_t)(o * 128 + fh * 2 + fo * 4))) =
                __floats2half2_rn(v.x, v.y);
        }
        if (t < 128) {
            const int half = t >> 6, f = t & 63;
            const float* ap = a + half * 64;
            float acc = 0.f;
#pragma unroll 8
            for (int o2 = 0; o2 < 64; o2++)
                acc += W32[o2 * 64 + f] * __ldg(&ap[o2]);
            if (half == 0) u1_s[f] = acc; else u2_s[f] = acc;
        }
    }
    __syncthreads();

    // phase 2: A = f16(h32) swizzled (overwrites W32); e partials (16 f's per thread)
    {
        const int r = t >> 2, fh = (t & 3) * 16;
        const float* src = h32 + r * 64 + fh;
        float acc1 = 0.f, acc2 = 0.f;
#pragma unroll
        for (int fo = 0; fo < 8; fo++) {
            float2 v = *(const float2*)(src + 2 * fo);
            int f = fh + 2 * fo;
            acc1 += v.x * u1_s[f] + v.y * u1_s[f + 1];
            acc2 += v.x * u2_s[f] + v.y * u2_s[f + 1];
            *(__half2*)((char*)reg1 + swz128((uint32_t)(r * 128 + fh * 2 + fo * 4))) =
                __floats2half2_rn(v.x, v.y);
        }
        acc1 += __shfl_xor_sync(0xffffffffu, acc1, 1);
        acc1 += __shfl_xor_sync(0xffffffffu, acc1, 2);
        acc2 += __shfl_xor_sync(0xffffffffu, acc2, 1);
        acc2 += __shfl_xor_sync(0xffffffffu, acc2, 2);
        if ((t & 3) == 0) {
            g_e1pack[row0 + r] = make_float4(acc1, __expf(acc1), __expf(0.2f * acc1), 0.f);
            g_e2pack[row0 + r] = make_float4(acc2, __expf(acc2), __expf(0.2f * acc2), 0.f);
        }
    }
    __syncthreads();

    // HMMA: 8 warps, wm = w&3 -> rows wm*16..+15, wn = w>>2 -> cols wn*32..+31
    float acc[4][4];
#pragma unroll
    for (int nf = 0; nf < 4; nf++)
#pragma unroll
        for (int c = 0; c < 4; c++) acc[nf][c] = 0.f;

    const int wm = w & 3, wn = w >> 2;
    {
        const uint32_t xv = (lane & 7) << 4;
        const uint32_t aRowOff = (uint32_t)(wm * 16 + (lane & 7) + ((lane >> 3) & 1) * 8) * 128;
        const uint32_t akbo    = ((lane >> 4) & 1) * 16;
        const uint32_t bRow4   = (uint32_t)(wn * 32 + ((lane >> 4) & 1) * 8 + (lane & 7)) * 128;
        const uint32_t bkb4    = ((lane >> 3) & 1) * 16;
#pragma unroll
        for (int kf = 0; kf < 4; kf++) {
            const uint32_t kb = kf * 32;
            uint32_t a4[4];
            ldsm_x4(a4[0], a4[1], a4[2], a4[3], r1b + aRowOff + ((kb + akbo) ^ xv));
#pragma unroll
            for (int p = 0; p < 2; p++) {
                uint32_t bfr[4];
                ldsm_x4(bfr[0], bfr[1], bfr[2], bfr[3],
                        Bsb + bRow4 + p * 2048 + ((kb + bkb4) ^ xv));
                mma16816(acc[2 * p],     a4, bfr);
                mma16816(acc[2 * p + 1], a4, bfr + 2);
            }
        }
    }
    __syncthreads();       // all phase-2 h32 reads done (pre-HMMA sync) + HMMA ldsm done

    // C frags -> f16 transpose tile tT[o][r] (stride 72)
    {
        const int r_lo = wm * 16 + (lane >> 2);
        const int r_hi = r_lo + 8;
#pragma unroll
        for (int nf = 0; nf < 4; nf++) {
            const int c0 = wn * 32 + nf * 8 + 2 * (lane & 3);
            tT[(c0 + 0) * 72 + r_lo] = __float2half_rn(acc[nf][0]);
            tT[(c0 + 1) * 72 + r_lo] = __float2half_rn(acc[nf][1]);
            tT[(c0 + 0) * 72 + r_hi] = __float2half_rn(acc[nf][2]);
            tT[(c0 + 1) * 72 + r_hi] = __float2half_rn(acc[nf][3]);
        }
    }
    __syncthreads();

    // write WhT: thread -> o = t>>2, r chunk = (t&3)*16, 2 x uint4
    {
        const int b  = row0 / Nn;
        const int i0 = row0 % Nn;
        const int o  = t >> 2;
        const int rp = (t & 3) * 16;
        __half* dst = g_WhT + ((size_t)b * Ff + o) * Nn + i0 + rp;
        *(uint4*)(dst)     = *(const uint4*)&tT[o * 72 + rp];
        *(uint4*)(dst + 8) = *(const uint4*)&tT[o * 72 + rp + 8];
    }
}

// ---------------------------------------------------------------------------
// Kernel 2: fused GAT via HMMA — exact R14 kernel (42.9 us measured).
// ---------------------------------------------------------------------------
__global__ __launch_bounds__(256, 2) void gat_hmma(float* __restrict__ out)
{
    __shared__ __align__(128) __half A_s[2][MTILE * 64];   // 2 x 8 KB
    __shared__ __align__(128) __half B_s[2][64 * 64];      // 2 x 8 KB
    __shared__ float e1_s[MTILE], E1p_s[MTILE], E1n_s[MTILE];
    __shared__ float Z_s[MTILE];

    const int t    = threadIdx.x;
    const int lane = t & 31;
    const int wid  = t >> 5;      // 0..7
    const int wm   = wid & 3;     // rows wm*16 .. +15
    const int wn   = wid >> 2;    // cols wn*32 .. +31
    const int i0   = blockIdx.x * MTILE;
    const int b    = blockIdx.y;

    if (t < MTILE) {
        float4 p = g_e1pack[(size_t)b * Nn + i0 + t];
        e1_s[t] = p.x; E1p_s[t] = p.y; E1n_s[t] = p.z;
    }
    __syncthreads();

    const uint32_t Abase = smem_u32(A_s);
    const uint32_t Bbase = smem_u32(B_s);

    const uint32_t xv = (lane & 7) << 4;
    const uint32_t aRowOff = (uint32_t)(wm * 16 + (lane & 7) + ((lane >> 3) & 1) * 8) * 128;
    const uint32_t akbo    = ((lane >> 4) & 1) * 16;
    const uint32_t bRow4   = (uint32_t)(wn * 32 + ((lane >> 4) & 1) * 8 + (lane & 7)) * 128;
    const uint32_t bkb4    = ((lane >> 3) & 1) * 16;

    const __half* whtB = g_WhT + (size_t)b * Ff * Nn;
    const float4* e2p  = g_e2pack + (size_t)b * Nn;

    const int bf1 = t >> 3, bc1 = t & 7;
    const int bf2 = (t + 256) >> 3;
    const uint32_t bDst1 = Bbase + swz128((uint32_t)(bf1 * 128 + bc1 * 16));
    const uint32_t bDst2 = Bbase + swz128((uint32_t)(bf2 * 128 + bc1 * 16));
    const __half* bSrc1 = whtB + (size_t)bf1 * Nn + bc1 * 8;
    const __half* bSrc2 = whtB + (size_t)bf2 * Nn + bc1 * 8;

#define CPB(S, BUF) do {                                  \
        cp16(bDst1 + (BUF) * 8192, bSrc1 + (S) * JT);     \
        cp16(bDst2 + (BUF) * 8192, bSrc2 + (S) * JT);     \
        CP_COMMIT();                                      \
    } while (0)

    float acc[4][4];
#pragma unroll
    for (int nf = 0; nf < 4; nf++)
#pragma unroll
        for (int c = 0; c < 4; c++) acc[nf][c] = 0.f;

    float zpart[8];
#pragma unroll
    for (int g = 0; g < 8; g++) zpart[g] = 0.f;

#define LOAD_SET(S, JP0, JP1, MM) do {                                           \
        JP0 = __ldg(&e2p[(S) * JT + 2 * lane]);                                  \
        JP1 = __ldg(&e2p[(S) * JT + 2 * lane + 1]);                              \
        _Pragma("unroll")                                                        \
        for (int g = 0; g < 8; g++)                                              \
            MM[g] = __ldg(&g_adjmask[(size_t)(i0 + wid * 8 + g) * (Nn / 64) + (S)]); \
    } while (0)

#define PGEN_C(JP0, JP1, MM, BUF) do {                                           \
        _Pragma("unroll")                                                        \
        for (int g = 0; g < 8; g++) {                                            \
            int i = wid * 8 + g;                                                 \
            float e1v = e1_s[i], e1pv = E1p_s[i], e1nv = E1n_s[i];               \
            float p0 = (e1v + JP0.x > 0.f) ? e1pv * JP0.y : e1nv * JP0.z;        \
            float p1 = (e1v + JP1.x > 0.f) ? e1pv * JP1.y : e1nv * JP1.z;        \
            p0 = ((MM[g] >> (2 * lane)) & 1ull)     ? p0 : 0.f;                  \
            p1 = ((MM[g] >> (2 * lane + 1)) & 1ull) ? p1 : 0.f;                  \
            __half2 ph = __floats2half2_rn(p0, p1);                              \
            float2 pf = __half22float2(ph);                                      \
            zpart[g] += pf.x + pf.y;                                             \
            *(__half2*)((char*)A_s + (BUF) * 8192 +                              \
                        swz128((uint32_t)(i * 128 + lane * 4))) = ph;            \
        }                                                                        \
    } while (0)

#define HMMA(BUF) do {                                                           \
        const uint32_t Ab_ = Abase + (BUF) * 8192;                               \
        const uint32_t Bb_ = Bbase + (BUF) * 8192;                               \
        _Pragma("unroll")                                                        \
        for (int kf = 0; kf < 4; kf++) {                                         \
            const uint32_t kb = kf * 32;                                         \
            uint32_t a4[4];                                                      \
            ldsm_x4(a4[0], a4[1], a4[2], a4[3], Ab_ + aRowOff + ((kb + akbo) ^ xv)); \
            _Pragma("unroll")                                                    \
            for (int p = 0; p < 2; p++) {                                        \
                uint32_t bfr[4];                                                 \
                ldsm_x4(bfr[0], bfr[1], bfr[2], bfr[3],                          \
                        Bb_ + bRow4 + p * 2048 + ((kb + bkb4) ^ xv));            \
                mma16816(acc[2 * p],     a4, bfr);                               \
                mma16816(acc[2 * p + 1], a4, bfr + 2);                           \
            }                                                                    \
        }                                                                        \
    } while (0)

    float4 jpA0, jpA1, jpB0, jpB1;
    ull mA[8], mB[8];

    CPB(0, 0);
    LOAD_SET(0, jpA0, jpA1, mA);
    PGEN_C(jpA0, jpA1, mA, 0);
    LOAD_SET(1, jpB0, jpB1, mB);

#pragma unroll 1
    for (int s = 0; s < NSTEPS; s += 2) {
        CP_WAIT0();
        __syncthreads();
        CPB(s + 1, 1);
        PGEN_C(jpB0, jpB1, mB, 1);
        if (s + 2 < NSTEPS) LOAD_SET(s + 2, jpA0, jpA1, mA);
        HMMA(0);

        CP_WAIT0();
        __syncthreads();
        if (s + 2 < NSTEPS) {
            CPB(s + 2, 0);
            PGEN_C(jpA0, jpA1, mA, 0);
            if (s + 3 < NSTEPS) LOAD_SET(s + 3, jpB0, jpB1, mB);
        }
        HMMA(1);
    }
#undef CPB
#undef LOAD_SET
#undef PGEN_C
#undef HMMA

#pragma unroll
    for (int g = 0; g < 8; g++) {
        float z = zpart[g];
#pragma unroll
        for (int off = 16; off; off >>= 1)
            z += __shfl_xor_sync(0xffffffffu, z, off);
        if (lane == 0) Z_s[wid * 8 + g] = z;
    }
    __syncthreads();

    {
        const int r_lo = wm * 16 + (lane >> 2);
        const int r_hi = r_lo + 8;
        const float zlo = 1.0f / Z_s[r_lo];
        const float zhi = 1.0f / Z_s[r_hi];
        float* olo = out + ((size_t)b * Nn + i0 + r_lo) * 64;
        float* ohi = out + ((size_t)b * Nn + i0 + r_hi) * 64;
#pragma unroll
        for (int nf = 0; nf < 4; nf++) {
            const int col = wn * 32 + nf * 8 + 2 * (lane & 3);
            float2 v;
            v.x = acc[nf][0] * zlo; v.y = acc[nf][1] * zlo;
            v.x = v.x > 0.f ? v.x : expm1f(v.x);
            v.y = v.y > 0.f ? v.y : expm1f(v.y);
            *(float2*)(olo + col) = v;
            v.x = acc[nf][2] * zhi; v.y = acc[nf][3] * zhi;
            v.x = v.x > 0.f ? v.x : expm1f(v.x);
            v.y = v.y > 0.f ? v.y : expm1f(v.y);
            *(float2*)(ohi + col) = v;
        }
    }
}

// ---------------------------------------------------------------------------
extern "C" void kernel_launch(void* const* d_in, const int* in_sizes, int n_in,
                              void* d_out, int out_size)
{
    const float* h = nullptr; const float* adj = nullptr;
    const float* W = nullptr; const float* a = nullptr;
    for (int i = 0; i < n_in; i++) {
        switch (in_sizes[i]) {
            case Bb * Nn * Ff: h   = (const float*)d_in[i]; break;
            case Nn * Nn:      adj = (const float*)d_in[i]; break;
            case Ff * Ff:      W   = (const float*)d_in[i]; break;
            case 2 * Ff:       a   = (const float*)d_in[i]; break;
            default: break;
        }
    }
    (void)out_size;

    prep_pack_kernel<<<PREP_CTAS + PACK_CTAS, 256>>>(h, W, a, adj);
    gat_hmma<<<dim3(Nn / MTILE, Bb), 256>>>((float*)d_out);
}